// round 14
// baseline (speedup 1.0000x reference)
#include <cuda_runtime.h>
#include <cstdint>

#define BB 1024
#define TT 4096
#define SS 8
#define EE 8
#define PHS 32              // scan steps per staging phase
#define NPH (TT / PHS)
#define CPB 8               // chains per block (4 warps x 2 chains SIMT)
#define THREADS 128

// Scratch (no cudaMalloc allowed)
__device__ float g_preds[(size_t)BB * TT * SS];   // 134 MB trajectory
__device__ float g_dt[TT];

using ull = unsigned long long;

// ---------------- f32x2 packed helpers ----------------
__device__ __forceinline__ ull pk2(float lo, float hi) {
    ull r; asm("mov.b64 %0, {%1, %2};" : "=l"(r) : "f"(lo), "f"(hi)); return r;
}
__device__ __forceinline__ void up2(ull a, float& lo, float& hi) {
    asm("mov.b64 {%0, %1}, %2;" : "=f"(lo), "=f"(hi) : "l"(a));
}
__device__ __forceinline__ ull fma2(ull a, ull b, ull c) {
    ull r; asm("fma.rn.f32x2 %0, %1, %2, %3;" : "=l"(r) : "l"(a), "l"(b), "l"(c)); return r;
}
__device__ __forceinline__ ull mul2(ull a, ull b) {
    ull r; asm("mul.rn.f32x2 %0, %1, %2;" : "=l"(r) : "l"(a), "l"(b)); return r;
}
__device__ __forceinline__ ull add2(ull a, ull b) {
    ull r; asm("add.rn.f32x2 %0, %1, %2;" : "=l"(r) : "l"(a), "l"(b)); return r;
}

// hardware tanh (MUFU.TANH): ~5e-4 max abs err, 1 instr
__device__ __forceinline__ float hw_tanh(float z) {
    float r; asm("tanh.approx.f32 %0, %1;" : "=f"(r) : "f"(z));
    return r;
}

__device__ __forceinline__ unsigned smem_u32(const void* p) {
    return (unsigned)__cvta_generic_to_shared(p);
}

__device__ __forceinline__ void cpa16(void* dst, const void* src) {
    asm volatile("cp.async.cg.shared.global [%0], [%1], 16;"
                 :: "r"(smem_u32(dst)), "l"(src));
}

// ---------------------------------------------------------------------------
__global__ void dt_kernel(const float* __restrict__ t) {
    int i = blockIdx.x * blockDim.x + threadIdx.x;
    if (i < TT) g_dt[i] = (i < TT - 1) ? (t[i + 1] - t[i]) : 0.0f;
}

// ---------------------------------------------------------------------------
// Sequential Euler scan: 16 lanes per chain, 2 chains per warp (SIMT),
// 4 warps/block, 512 warps. Lane u (=lane&15) owns hidden units j = u, u+16.
// Reduction: permuted-slot reduce-scatter + 3-round butterfly + all-gather
// (20 SHFL32/step). preds staged in smem (STS.128) and drained per-phase via
// cp.async.bulk (TMA pipe) instead of per-step STG.128 (12-cy issue each).
__global__ __launch_bounds__(THREADS, 1)
void scan_kernel(const float* __restrict__ x,    // [B,T,E]
                 const float* __restrict__ y0,   // [B,S]
                 const float* __restrict__ Wr1,  // [S+E, 32]
                 const float* __restrict__ br1,  // [32]
                 const float* __restrict__ Wr2,  // [32, S]
                 const float* __restrict__ br2)  // [S]
{
    __shared__ __align__(16) float sx[2][CPB][PHS * EE];      // 16 KB x-staging
    __shared__ __align__(16) float spreds[2][CPB][PHS * SS];  // 16 KB preds staging
    __shared__ __align__(16) float sdt[2][PHS];               // dt staging

    const int tid  = threadIdx.x;
    const int lane = tid & 31;
    const int wid  = tid >> 5;
    const int u    = lane & 15;                 // lane within 16-group
    const int grp  = lane >> 4;                 // chain within warp
    const int cloc = wid * 2 + grp;             // chain slot in block
    const int chain = blockIdx.x * CPB + cloc;

    const int o = (u >> 3) & 1;                 // own-half selector
    int cpm[4];                                 // slot k -> component pair
    cpm[0] = 2 * o;       cpm[1] = 2 * o + 1;
    cpm[2] = 2 * (1 - o); cpm[3] = 2 * (1 - o) + 1;

    // ---- register-resident weights (packed pairs), units j = u + 16m ----
    ull wy[2][4], we[2][4], w2p[2][4], b1p[2];
#pragma unroll
    for (int m = 0; m < 2; ++m) {
        const int j = u + 16 * m;
#pragma unroll
        for (int k = 0; k < 4; ++k) {
            const int cp = cpm[k];
            wy[m][k]  = pk2(Wr1[(2 * cp) * 32 + j],    Wr1[(2 * cp + 1) * 32 + j]);
            we[m][k]  = pk2(Wr1[(8 + 2 * k) * 32 + j], Wr1[(9 + 2 * k) * 32 + j]);
            w2p[m][k] = pk2(Wr2[j * 8 + 2 * cp],       Wr2[j * 8 + 2 * cp + 1]);
        }
        b1p[m] = pk2(br1[j], 0.0f);   // bias in lo slot; hi stays 0 through chain
    }
    ull b2o[2];                        // own-half br2 pairs (slots 0,1)
    b2o[0] = pk2(br2[2 * cpm[0]], br2[2 * cpm[0] + 1]);
    b2o[1] = pk2(br2[2 * cpm[1]], br2[2 * cpm[1] + 1]);

    // ---- initial state into permuted slots ----
    ull yp[4];
    {
        const float4* q = (const float4*)(y0 + (size_t)chain * SS);
        float4 A = q[0], B = q[1];
        ull nat[4];
        nat[0] = pk2(A.x, A.y); nat[1] = pk2(A.z, A.w);
        nat[2] = pk2(B.x, B.y); nat[3] = pk2(B.z, B.w);
#pragma unroll
        for (int k = 0; k < 4; ++k) yp[k] = nat[cpm[k]];
    }

    // ---- x/dt staging: 8 chains x 256 floats = 512 x 16B; 4 per thread ----
    auto issue = [&](int ph, int buf) {
#pragma unroll
        for (int q = 0; q < 4; ++q) {
            const int idx = tid + q * THREADS;    // 0..511
            const int c   = idx >> 6;             // chain
            const int off = idx & 63;             // 16B chunk within chain
            cpa16(&sx[buf][c][off * 4],
                  x + ((size_t)(blockIdx.x * CPB + c) * TT + (size_t)ph * PHS) * EE + off * 4);
        }
        if (tid < 8) cpa16(&sdt[buf][tid * 4], g_dt + ph * PHS + tid * 4);
        asm volatile("cp.async.commit_group;");
    };

    issue(0, 0);
    asm volatile("cp.async.wait_group 0;");
    __syncthreads();

    int buf = 0;

    for (int ph = 0; ph < NPH; ++ph) {
        if (ph + 1 < NPH) {
            issue(ph + 1, buf ^ 1);
            asm volatile("cp.async.wait_group 1;");
        }
        // spreds[buf] was last handed to the bulk engine 2 phases ago; make
        // sure that group completed before we overwrite the buffer.
        if (tid < CPB) asm volatile("cp.async.bulk.wait_group 1;");
        __syncthreads();
        const float* eb  = sx[buf][cloc];
        const float* dtb = sdt[buf];
        float* sp = &spreds[buf][cloc][0];

#pragma unroll 4
        for (int i = 0; i < PHS; ++i) {
            // preds[b][t] = state BEFORE this step's update (preds[0] = y0).
            // Lane u==0 has o=0 -> cpm identity -> natural order. STS.128 x2.
            if (u == 0) {
                float f0, f1, f2, f3, f4, f5, f6, f7;
                up2(yp[0], f0, f1); up2(yp[1], f2, f3);
                up2(yp[2], f4, f5); up2(yp[3], f6, f7);
                float4* oo = (float4*)(sp + i * SS);
                oo[0] = make_float4(f0, f1, f2, f3);
                oo[1] = make_float4(f4, f5, f6, f7);
            }

            const float dt = dtb[i];
            const ull dt2 = pk2(dt, dt);
            // prefold y + dt*br2 on own half — parallel with z-dot
            const ull ybo0 = fma2(dt2, b2o[0], yp[0]);
            const ull ybo1 = fma2(dt2, b2o[1], yp[1]);

            // e as 2 x LDS.128 (4 packed pairs, natural order)
            const ulonglong2* ev = (const ulonglong2*)(eb + i * 8);
            const ulonglong2 eA = ev[0], eB = ev[1];

            // z_j = br1 + e.We + y.Wy — two parallel 4-deep chains + merge
            float h[2];
#pragma unroll
            for (int m = 0; m < 2; ++m) {
                ull c = fma2(eA.x, we[m][0], b1p[m]);
                ull a = mul2(yp[0], wy[m][0]);
                c = fma2(eA.y, we[m][1], c);
                a = fma2(yp[1], wy[m][1], a);
                c = fma2(eB.x, we[m][2], c);
                a = fma2(yp[2], wy[m][2], a);
                c = fma2(eB.y, we[m][3], c);
                a = fma2(yp[3], wy[m][3], a);
                const ull s = add2(a, c);
                float lo, hi; up2(s, lo, hi);
                h[m] = hw_tanh(lo + hi);
            }

            // partial rhs pairs (permuted slot order)
            const ull h0d = pk2(h[0], h[0]);
            const ull h1d = pk2(h[1], h[1]);
            ull p0 = fma2(h1d, w2p[1][0], mul2(h0d, w2p[0][0]));
            ull p1 = fma2(h1d, w2p[1][1], mul2(h0d, w2p[0][1]));
            ull p2 = fma2(h1d, w2p[1][2], mul2(h0d, w2p[0][2]));
            ull p3 = fma2(h1d, w2p[1][3], mul2(h0d, w2p[0][3]));

            // reduce-scatter (mask 8): slots 2,3 are the partner's own half
            ull q0 = add2(p0, __shfl_xor_sync(0xffffffffu, p2, 8));
            ull q1 = add2(p1, __shfl_xor_sync(0xffffffffu, p3, 8));

            // 3-round butterfly within the 8-lane subgroup
#pragma unroll
            for (int mask = 1; mask < 8; mask <<= 1) {
                q0 = add2(q0, __shfl_xor_sync(0xffffffffu, q0, mask));
                q1 = add2(q1, __shfl_xor_sync(0xffffffffu, q1, mask));
            }

            // Euler update, own half only (dt[T-1]=0 -> final step no-op)
            yp[0] = fma2(dt2, q0, ybo0);
            yp[1] = fma2(dt2, q1, ybo1);

            // all-gather (mask 8): partner's updated own half = my other half
            yp[2] = __shfl_xor_sync(0xffffffffu, yp[0], 8);
            yp[3] = __shfl_xor_sync(0xffffffffu, yp[1], 8);
        }
        __syncthreads();     // STS of spreds[buf] + reads of sx[buf] complete

        // drain this phase's preds via the TMA/bulk pipe (off critical path)
        if (tid < CPB) {
            asm volatile("fence.proxy.async.shared::cta;" ::: "memory");
            float* gdst = g_preds + (size_t)(blockIdx.x * CPB + tid) * TT * SS
                                  + (size_t)ph * PHS * SS;
            asm volatile("cp.async.bulk.global.shared::cta.bulk_group [%0], [%1], %2;"
                         :: "l"(gdst), "r"(smem_u32(&spreds[buf][tid][0])),
                            "r"(PHS * SS * 4) : "memory");
            asm volatile("cp.async.bulk.commit_group;");
        }
        buf ^= 1;
    }

    // make all outstanding bulk stores visible before kernel exit
    if (tid < CPB) asm volatile("cp.async.bulk.wait_group 0;");
}

// ---------------------------------------------------------------------------
// Head: out = relu(preds @ W1 + b1) @ W2 + b2 — fully register-resident weights
__global__ __launch_bounds__(256)
void head_kernel(const float* __restrict__ W1, const float* __restrict__ b1,
                 const float* __restrict__ W2, const float* __restrict__ b2,
                 float* __restrict__ out)
{
    float w1[8][10], bb1[10], w2[10][2];
#pragma unroll
    for (int s = 0; s < 8; ++s)
#pragma unroll
        for (int i = 0; i < 10; ++i) w1[s][i] = __ldg(&W1[s * 10 + i]);
#pragma unroll
    for (int i = 0; i < 10; ++i) {
        bb1[i]   = __ldg(&b1[i]);
        w2[i][0] = __ldg(&W2[i * 2 + 0]);
        w2[i][1] = __ldg(&W2[i * 2 + 1]);
    }
    const float c0 = __ldg(&b2[0]), c1 = __ldg(&b2[1]);

    const int nt  = gridDim.x * blockDim.x;
    const int tid = blockIdx.x * blockDim.x + threadIdx.x;
    const int NPOS = BB * TT;

    for (int pos = tid; pos < NPOS; pos += nt) {
        const float4* ypt = (const float4*)(g_preds + (size_t)pos * SS);
        const float4 A = ypt[0], B = ypt[1];
        const float yv[8] = {A.x, A.y, A.z, A.w, B.x, B.y, B.z, B.w};
        float o0 = c0, o1 = c1;
#pragma unroll
        for (int i = 0; i < 10; ++i) {
            float hz = bb1[i];
#pragma unroll
            for (int s = 0; s < 8; ++s) hz = fmaf(yv[s], w1[s][i], hz);
            hz = fmaxf(hz, 0.0f);
            o0 = fmaf(hz, w2[i][0], o0);
            o1 = fmaf(hz, w2[i][1], o1);
        }
        *(float2*)(out + (size_t)pos * 2) = make_float2(o0, o1);
    }
}

// ---------------------------------------------------------------------------
extern "C" void kernel_launch(void* const* d_in, const int* in_sizes, int n_in,
                              void* d_out, int out_size) {
    const float* x   = (const float*)d_in[0];
    const float* t   = (const float*)d_in[1];
    const float* y0  = (const float*)d_in[2];
    const float* Wr1 = (const float*)d_in[3];
    const float* br1 = (const float*)d_in[4];
    const float* Wr2 = (const float*)d_in[5];
    const float* br2 = (const float*)d_in[6];
    const float* W1  = (const float*)d_in[7];
    const float* b1  = (const float*)d_in[8];
    const float* W2  = (const float*)d_in[9];
    const float* b2  = (const float*)d_in[10];
    float* out = (float*)d_out;

    dt_kernel<<<16, 256>>>(t);
    scan_kernel<<<BB / CPB, THREADS>>>(x, y0, Wr1, br1, Wr2, br2);
    head_kernel<<<2048, 256>>>(W1, b1, W2, b2, out);
}

// round 15
// speedup vs baseline: 1.0749x; 1.0749x over previous
#include <cuda_runtime.h>
#include <cstdint>

#define BB 1024
#define TT 4096
#define SS 8
#define EE 8
#define PHS 64              // scan steps per cp.async phase
#define NPH (TT / PHS)
#define CPB 8               // chains per block (4 warps x 2 chains SIMT)
#define THREADS 128

// Scratch (no cudaMalloc allowed)
__device__ float g_preds[(size_t)BB * TT * SS];   // 134 MB trajectory
__device__ float g_dt[TT];

using ull = unsigned long long;

// ---------------- f32x2 packed helpers ----------------
__device__ __forceinline__ ull pk2(float lo, float hi) {
    ull r; asm("mov.b64 %0, {%1, %2};" : "=l"(r) : "f"(lo), "f"(hi)); return r;
}
__device__ __forceinline__ void up2(ull a, float& lo, float& hi) {
    asm("mov.b64 {%0, %1}, %2;" : "=f"(lo), "=f"(hi) : "l"(a));
}
__device__ __forceinline__ ull fma2(ull a, ull b, ull c) {
    ull r; asm("fma.rn.f32x2 %0, %1, %2, %3;" : "=l"(r) : "l"(a), "l"(b), "l"(c)); return r;
}
__device__ __forceinline__ ull mul2(ull a, ull b) {
    ull r; asm("mul.rn.f32x2 %0, %1, %2;" : "=l"(r) : "l"(a), "l"(b)); return r;
}
__device__ __forceinline__ ull add2(ull a, ull b) {
    ull r; asm("add.rn.f32x2 %0, %1, %2;" : "=l"(r) : "l"(a), "l"(b)); return r;
}

// hardware tanh (MUFU.TANH): ~5e-4 max abs err, 1 instr
__device__ __forceinline__ float hw_tanh(float z) {
    float r; asm("tanh.approx.f32 %0, %1;" : "=f"(r) : "f"(z));
    return r;
}

__device__ __forceinline__ void cpa16(void* dst, const void* src) {
    unsigned s = (unsigned)__cvta_generic_to_shared(dst);
    asm volatile("cp.async.cg.shared.global [%0], [%1], 16;" :: "r"(s), "l"(src));
}

// ---------------------------------------------------------------------------
__global__ void dt_kernel(const float* __restrict__ t) {
    int i = blockIdx.x * blockDim.x + threadIdx.x;
    if (i < TT) g_dt[i] = (i < TT - 1) ? (t[i + 1] - t[i]) : 0.0f;
}

// ---------------------------------------------------------------------------
// Sequential Euler scan: 16 lanes per chain, 2 chains per warp (SIMT),
// 4 warps/block, 512 warps. Lane u (=lane&15) owns hidden units j = u, u+16.
//
// Reduction (permuted slots, 20 SHFL32/step):
//   reduce-scatter (mask 8)  ->  3-round butterfly  ->  own-half update
//   ->  all-gather (mask 8)
// This round: p2,p3 computed FIRST so the RS shuffles issue early; the preds
// STG is placed inside the RS shuffle-wait window; unroll 8.
__global__ __launch_bounds__(THREADS, 1)
void scan_kernel(const float* __restrict__ x,    // [B,T,E]
                 const float* __restrict__ y0,   // [B,S]
                 const float* __restrict__ Wr1,  // [S+E, 32]
                 const float* __restrict__ br1,  // [32]
                 const float* __restrict__ Wr2,  // [32, S]
                 const float* __restrict__ br2)  // [S]
{
    __shared__ __align__(16) float sx[2][CPB][PHS * EE];  // 32 KB x-staging
    __shared__ __align__(16) float sdt[2][PHS];           // dt staging

    const int tid  = threadIdx.x;
    const int lane = tid & 31;
    const int wid  = tid >> 5;
    const int u    = lane & 15;                 // lane within 16-group
    const int grp  = lane >> 4;                 // chain within warp
    const int cloc = wid * 2 + grp;             // chain slot in block
    const int chain = blockIdx.x * CPB + cloc;

    const int o = (u >> 3) & 1;                 // own-half selector
    int cpm[4];                                 // slot k -> component pair
    cpm[0] = 2 * o;       cpm[1] = 2 * o + 1;
    cpm[2] = 2 * (1 - o); cpm[3] = 2 * (1 - o) + 1;

    // ---- register-resident weights (packed pairs), units j = u + 16m ----
    ull wy[2][4], we[2][4], w2p[2][4], b1p[2];
#pragma unroll
    for (int m = 0; m < 2; ++m) {
        const int j = u + 16 * m;
#pragma unroll
        for (int k = 0; k < 4; ++k) {
            const int cp = cpm[k];
            wy[m][k]  = pk2(Wr1[(2 * cp) * 32 + j],    Wr1[(2 * cp + 1) * 32 + j]);
            we[m][k]  = pk2(Wr1[(8 + 2 * k) * 32 + j], Wr1[(9 + 2 * k) * 32 + j]);
            w2p[m][k] = pk2(Wr2[j * 8 + 2 * cp],       Wr2[j * 8 + 2 * cp + 1]);
        }
        b1p[m] = pk2(br1[j], 0.0f);   // bias in lo slot; hi stays 0 through chain
    }
    ull b2o[2];                        // own-half br2 pairs (slots 0,1)
    b2o[0] = pk2(br2[2 * cpm[0]], br2[2 * cpm[0] + 1]);
    b2o[1] = pk2(br2[2 * cpm[1]], br2[2 * cpm[1] + 1]);

    // ---- initial state into permuted slots ----
    ull yp[4];
    {
        const float4* q = (const float4*)(y0 + (size_t)chain * SS);
        float4 A = q[0], B = q[1];
        ull nat[4];
        nat[0] = pk2(A.x, A.y); nat[1] = pk2(A.z, A.w);
        nat[2] = pk2(B.x, B.y); nat[3] = pk2(B.z, B.w);
#pragma unroll
        for (int k = 0; k < 4; ++k) yp[k] = nat[cpm[k]];
    }

    // ---- phase staging: 8 chains x 512 floats = 1024 x 16B; 8 per thread ----
    auto issue = [&](int ph, int buf) {
#pragma unroll
        for (int q = 0; q < 8; ++q) {
            const int idx = tid + q * THREADS;    // 0..1023
            const int c   = idx >> 7;             // chain
            const int off = idx & 127;            // 16B chunk within chain
            cpa16(&sx[buf][c][off * 4],
                  x + ((size_t)(blockIdx.x * CPB + c) * TT + (size_t)ph * PHS) * EE + off * 4);
        }
        if (tid < 16) cpa16(&sdt[buf][tid * 4], g_dt + ph * PHS + tid * 4);
        asm volatile("cp.async.commit_group;");
    };

    issue(0, 0);
    asm volatile("cp.async.wait_group 0;");
    __syncthreads();

    float* pp = g_preds + (size_t)chain * TT * SS;
    int buf = 0;

    for (int ph = 0; ph < NPH; ++ph) {
        if (ph + 1 < NPH) {
            issue(ph + 1, buf ^ 1);
            asm volatile("cp.async.wait_group 1;");
        }
        __syncthreads();
        const float* eb  = sx[buf][cloc];
        const float* dtb = sdt[buf];

#pragma unroll 8
        for (int i = 0; i < PHS; ++i) {
            const float dt = dtb[i];
            const ull dt2 = pk2(dt, dt);
            // prefold y + dt*br2 on own half — parallel with z-dot
            const ull ybo0 = fma2(dt2, b2o[0], yp[0]);
            const ull ybo1 = fma2(dt2, b2o[1], yp[1]);

            // e as 2 x LDS.128 (4 packed pairs, natural order)
            const ulonglong2* ev = (const ulonglong2*)(eb + i * 8);
            const ulonglong2 eA = ev[0], eB = ev[1];

            // z_j = br1 + e.We + y.Wy — two parallel 4-deep chains + merge
            float h[2];
#pragma unroll
            for (int m = 0; m < 2; ++m) {
                ull c = fma2(eA.x, we[m][0], b1p[m]);
                ull a = mul2(yp[0], wy[m][0]);
                c = fma2(eA.y, we[m][1], c);
                a = fma2(yp[1], wy[m][1], a);
                c = fma2(eB.x, we[m][2], c);
                a = fma2(yp[2], wy[m][2], a);
                c = fma2(eB.y, we[m][3], c);
                a = fma2(yp[3], wy[m][3], a);
                const ull s = add2(a, c);
                float lo, hi; up2(s, lo, hi);
                h[m] = hw_tanh(lo + hi);
            }

            // partial rhs pairs (permuted slot order) — p2,p3 FIRST so the
            // reduce-scatter shuffles can issue as early as possible.
            const ull h0d = pk2(h[0], h[0]);
            const ull h1d = pk2(h[1], h[1]);
            ull p2 = fma2(h1d, w2p[1][2], mul2(h0d, w2p[0][2]));
            ull p3 = fma2(h1d, w2p[1][3], mul2(h0d, w2p[0][3]));

            // reduce-scatter (mask 8): slots 2,3 are the partner's own half
            const ull t2 = __shfl_xor_sync(0xffffffffu, p2, 8);
            const ull t3 = __shfl_xor_sync(0xffffffffu, p3, 8);

            // --- independent work inside the RS shuffle-wait window ---
            // preds[b][t] = state BEFORE this step's update (preds[0] = y0).
            // Lane u==0 has o=0 -> cpm identity -> natural order.
            if (u == 0) {
                float f0, f1, f2, f3, f4, f5, f6, f7;
                up2(yp[0], f0, f1); up2(yp[1], f2, f3);
                up2(yp[2], f4, f5); up2(yp[3], f6, f7);
                float4* oo = (float4*)pp;
                oo[0] = make_float4(f0, f1, f2, f3);
                oo[1] = make_float4(f4, f5, f6, f7);
            }
            pp += SS;

            ull p0 = fma2(h1d, w2p[1][0], mul2(h0d, w2p[0][0]));
            ull p1 = fma2(h1d, w2p[1][1], mul2(h0d, w2p[0][1]));
            // --- end fill ---

            ull q0 = add2(p0, t2);
            ull q1 = add2(p1, t3);

            // 3-round butterfly within the 8-lane subgroup
#pragma unroll
            for (int mask = 1; mask < 8; mask <<= 1) {
                q0 = add2(q0, __shfl_xor_sync(0xffffffffu, q0, mask));
                q1 = add2(q1, __shfl_xor_sync(0xffffffffu, q1, mask));
            }

            // Euler update, own half only (dt[T-1]=0 -> final step no-op)
            yp[0] = fma2(dt2, q0, ybo0);
            yp[1] = fma2(dt2, q1, ybo1);

            // all-gather (mask 8): partner's updated own half = my other half
            yp[2] = __shfl_xor_sync(0xffffffffu, yp[0], 8);
            yp[3] = __shfl_xor_sync(0xffffffffu, yp[1], 8);
        }
        __syncthreads();     // all reads of sx[buf] done before next issue overwrites it
        buf ^= 1;
    }
}

// ---------------------------------------------------------------------------
// Head: out = relu(preds @ W1 + b1) @ W2 + b2 — fully register-resident weights
__global__ __launch_bounds__(256)
void head_kernel(const float* __restrict__ W1, const float* __restrict__ b1,
                 const float* __restrict__ W2, const float* __restrict__ b2,
                 float* __restrict__ out)
{
    float w1[8][10], bb1[10], w2[10][2];
#pragma unroll
    for (int s = 0; s < 8; ++s)
#pragma unroll
        for (int i = 0; i < 10; ++i) w1[s][i] = __ldg(&W1[s * 10 + i]);
#pragma unroll
    for (int i = 0; i < 10; ++i) {
        bb1[i]   = __ldg(&b1[i]);
        w2[i][0] = __ldg(&W2[i * 2 + 0]);
        w2[i][1] = __ldg(&W2[i * 2 + 1]);
    }
    const float c0 = __ldg(&b2[0]), c1 = __ldg(&b2[1]);

    const int nt  = gridDim.x * blockDim.x;
    const int tid = blockIdx.x * blockDim.x + threadIdx.x;
    const int NPOS = BB * TT;

    for (int pos = tid; pos < NPOS; pos += nt) {
        const float4* ypt = (const float4*)(g_preds + (size_t)pos * SS);
        const float4 A = ypt[0], B = ypt[1];
        const float yv[8] = {A.x, A.y, A.z, A.w, B.x, B.y, B.z, B.w};
        float o0 = c0, o1 = c1;
#pragma unroll
        for (int i = 0; i < 10; ++i) {
            float hz = bb1[i];
#pragma unroll
            for (int s = 0; s < 8; ++s) hz = fmaf(yv[s], w1[s][i], hz);
            hz = fmaxf(hz, 0.0f);
            o0 = fmaf(hz, w2[i][0], o0);
            o1 = fmaf(hz, w2[i][1], o1);
        }
        *(float2*)(out + (size_t)pos * 2) = make_float2(o0, o1);
    }
}

// ---------------------------------------------------------------------------
extern "C" void kernel_launch(void* const* d_in, const int* in_sizes, int n_in,
                              void* d_out, int out_size) {
    const float* x   = (const float*)d_in[0];
    const float* t   = (const float*)d_in[1];
    const float* y0  = (const float*)d_in[2];
    const float* Wr1 = (const float*)d_in[3];
    const float* br1 = (const float*)d_in[4];
    const float* Wr2 = (const float*)d_in[5];
    const float* br2 = (const float*)d_in[6];
    const float* W1  = (const float*)d_in[7];
    const float* b1  = (const float*)d_in[8];
    const float* W2  = (const float*)d_in[9];
    const float* b2  = (const float*)d_in[10];
    float* out = (float*)d_out;

    dt_kernel<<<16, 256>>>(t);
    scan_kernel<<<BB / CPB, THREADS>>>(x, y0, Wr1, br1, Wr2, br2);
    head_kernel<<<2048, 256>>>(W1, b1, W2, b2, out);
}